// round 10
// baseline (speedup 1.0000x reference)
#include <cuda_runtime.h>
#include <cstdint>

#define DI __device__ __forceinline__

DI float fq_q(float x, float s) {
    float q = rintf(__fdiv_rn(x, s));
    return fminf(fmaxf(q, -128.0f), 127.0f);
}
DI float fq(float x, float s) { return fq_q(x, s) * s; }
DI int sbyte(int w, int k) { return (int)((signed char)(w >> (8 * k))); }

#define WSP 264
#define HSP 260
#define ORG (3 * 264 + 3)

// ---------------- scratch ----------------
__device__ __align__(16) signed char g_pad16[(size_t)32 * HSP * WSP * 16];
__device__ __align__(16) signed char g_pad32[(size_t)32 * HSP * WSP * 32];
__device__ __align__(16) signed char g_c3[(size_t)32 * 254 * 254 * 32];
__device__ __align__(16) signed char g_pool[(size_t)32 * 127 * 132 * 32];
__device__ __align__(16) signed char g_c4[(size_t)32 * 125 * 125 * 16];
__device__ __align__(16) signed char g_in0[(size_t)32 * 256 * 256];
__device__ __align__(16) int g_qw1[9 * 16];
__device__ __align__(16) signed char g_qw2[5 * 32 * 32];    // [chunk][oc][32B] paired taps
__device__ __align__(16) signed char g_qw3[25 * 32 * 32];   // [tap][oc][ic]
__device__ __align__(16) signed char g_qw4[9 * 16 * 32];    // [tap][oc][ic]
__device__ float g_qwc[160], g_wscale[8], g_feat[512];

DI void mma_k32(int d[4], unsigned a0, unsigned a1, unsigned a2, unsigned a3,
                unsigned b0, unsigned b1) {
    asm volatile(
        "mma.sync.aligned.m16n8k32.row.col.s32.s8.s8.s32 "
        "{%0,%1,%2,%3}, {%4,%5,%6,%7}, {%8,%9}, {%0,%1,%2,%3};\n"
        : "+r"(d[0]), "+r"(d[1]), "+r"(d[2]), "+r"(d[3])
        : "r"(a0), "r"(a1), "r"(a2), "r"(a3), "r"(b0), "r"(b1));
}

// ---------------- prep ----------------
DI float bmax(const float* w, int n, float* red) {
    float m = 0.0f;
    for (int i = threadIdx.x; i < n; i += 256) m = fmaxf(m, fabsf(w[i]));
    red[threadIdx.x] = m;
    __syncthreads();
    for (int s = 128; s > 0; s >>= 1) {
        if (threadIdx.x < s) red[threadIdx.x] = fmaxf(red[threadIdx.x], red[threadIdx.x + s]);
        __syncthreads();
    }
    return red[0];
}

__global__ void prep_kernel(const float* __restrict__ x, const float* __restrict__ w1,
                            const float* __restrict__ w2, const float* __restrict__ w3,
                            const float* __restrict__ w4, const float* __restrict__ wc,
                            const float* __restrict__ sc) {
    __shared__ float red[256];
    const int blk = blockIdx.x, tid = threadIdx.x;
    if (blk < 2048) {
        int i = blk * 256 + tid;
        float4 v = ((const float4*)x)[i];
        float inv = __frcp_rn(sc[0]);
        int c0 = max(min(__float2int_rn(v.x * inv), 127), -128);
        int c1 = max(min(__float2int_rn(v.y * inv), 127), -128);
        int c2 = max(min(__float2int_rn(v.z * inv), 127), -128);
        int c3 = max(min(__float2int_rn(v.w * inv), 127), -128);
        ((int*)g_in0)[i] = (c0 & 0xFF) | ((c1 & 0xFF) << 8) | ((c2 & 0xFF) << 16) |
                           ((c3 & 0xFF) << 24);
    } else if (blk == 2048) {
        float s = __fdiv_rn(bmax(w1, 144, red), 127.0f);
        if (tid == 0) g_wscale[0] = s;
        for (int i = tid; i < 144; i += 256) g_qw1[(i % 9) * 16 + i / 9] = (int)fq_q(w1[i], s);
    } else if (blk == 2049) {  // conv2: 5 paired chunks [c][oc][32B]
        float s = __fdiv_rn(bmax(w2, 4608, red), 127.0f);
        if (tid == 0) g_wscale[1] = s;
        for (int i = tid; i < 5120; i += 256) {
            int j = i & 31, oc = (i >> 5) & 31, c = i >> 10;
            int tap = 2 * c + (j >= 16), ic = j & 15;
            signed char v = 0;
            if (tap < 9)
                v = (signed char)(int)fq_q(w2[((oc * 16 + ic) * 3 + tap / 3) * 3 + tap % 3], s);
            g_qw2[i] = v;
        }
    } else if (blk == 2050) {
        float s = __fdiv_rn(bmax(w3, 25600, red), 127.0f);
        if (tid == 0) g_wscale[2] = s;
        for (int i = tid; i < 25600; i += 256) {
            int ic = i & 31, oc = (i >> 5) & 31, tap = i >> 10;
            g_qw3[i] = (signed char)(int)fq_q(w3[((oc * 32 + ic) * 5 + tap / 5) * 5 + tap % 5], s);
        }
    } else if (blk == 2051) {
        float s = __fdiv_rn(bmax(w4, 4608, red), 127.0f);
        if (tid == 0) g_wscale[3] = s;
        for (int i = tid; i < 4608; i += 256) {
            int ic = i & 31, oc = (i >> 5) & 15, tap = i >> 9;
            g_qw4[i] = (signed char)(int)fq_q(w4[((oc * 32 + ic) * 3 + tap / 3) * 3 + tap % 3], s);
        }
    } else if (blk == 2052) {
        float s = __fdiv_rn(bmax(wc, 160, red), 127.0f);
        for (int i = tid; i < 160; i += 256) g_qwc[(i % 16) * 10 + i / 16] = fq_q(wc[i], s) * s;
    } else {
        int idx = (blk - 2053) * 256 + tid;
        const int ITEMS = 32 * 4124;
        int which = idx >= ITEMS;
        if (which) idx -= ITEMS;
        int b = idx / 4124, i = idx % 4124, pr, pc;
        if (i < 1584) { pc = i % 264; int r = i / 264; pr = (r < 3) ? r : 254 + r; }
        else { int j = i - 1584; pr = 3 + j / 10; int c = j % 10; pc = (c < 3) ? c : 254 + c; }
        size_t px = ((size_t)b * HSP + pr) * WSP + pc;
        uint4 z = make_uint4(0, 0, 0, 0);
        if (!which) {
            *(uint4*)(g_pad16 + px * 16) = z;
        } else {
            uint4* d = (uint4*)(g_pad32 + px * 32);
            d[0] = z; d[1] = z;
        }
    }
}

// ---------------- conv1 ----------------
__global__ void __launch_bounds__(256) conv1_kernel(const float* __restrict__ bias,
                                                    const float* __restrict__ sc) {
    __shared__ int wsm[144];
    __shared__ signed char lut[128];
    __shared__ float bsm[16];
    const int tid = threadIdx.x;
    const float sa = sc[1], sb = sc[2];
    if (tid < 128) lut[tid] = (signed char)(int)fq_q((float)tid * sa, sb);
    if (tid < 144) wsm[tid] = g_qw1[tid];
    if (tid >= 144 && tid < 160) bsm[tid - 144] = bias[tid - 144];
    __syncthreads();
    int idx = blockIdx.x * 256 + tid;
    if (idx >= 32 * 254 * 254) return;
    int x = idx % 254, y = (idx / 254) % 254, b = idx / (254 * 254);
    const signed char* base = g_in0 + (size_t)b * 65536;
    int v[9];
#pragma unroll
    for (int ky = 0; ky < 3; ky++)
#pragma unroll
        for (int kx = 0; kx < 3; kx++)
            v[ky * 3 + kx] = (int)base[(size_t)(y + ky) * 256 + x + kx];
    int acc[16];
#pragma unroll
    for (int j = 0; j < 16; j++) acc[j] = 0;
#pragma unroll
    for (int t = 0; t < 9; t++)
#pragma unroll
        for (int j = 0; j < 16; j++) acc[j] += v[t] * wsm[t * 16 + j];
    const float csa = __fdiv_rn(sc[0] * g_wscale[0], sa);
    unsigned wds[4];
#pragma unroll
    for (int g = 0; g < 4; g++) {
        unsigned wd = 0;
#pragma unroll
        for (int k = 0; k < 4; k++) {
            int j = g * 4 + k;
            int c = __float2int_rn(fmaf((float)acc[j], csa, __fdiv_rn(bsm[j], sa)));
            wd |= ((unsigned)(unsigned char)lut[max(min(c, 127), 0)]) << (8 * k);
        }
        wds[g] = wd;
    }
    *(uint4*)(g_pad16 + (((size_t)b * HSP + y + 3) * WSP + x + 3) * 16) =
        make_uint4(wds[0], wds[1], wds[2], wds[3]);
}

// ---------------- hybrid conv: blocks < SPLIT run IMMA, rest run dp4a ----------------
// chunk c = 32 K-bytes = two 16B halves with offsets o0/o1 (identical semantics both paths)
template <int PXB, int OC, int K, int NCH, int YB>
__global__ void __launch_bounds__(128) conv_hyb_kernel(
    const signed char* __restrict__ in, long BSi, int RSi, int PAD,
    const signed char* __restrict__ wq, const float* __restrict__ bias,
    signed char* __restrict__ out, long BSo, int RSo, int Wout, int Hout,
    const float* __restrict__ sc, const float* __restrict__ wsc,
    int s_in, int s_a, int s_b, int SPLIT) {
    constexpr int NTL = OC / 8;
    constexpr int KK = K * K;
    constexpr int NWB = NCH * OC * 32;

    __shared__ int wsm[NWB / 4];
    __shared__ signed char lut[128];
    __shared__ __align__(16) signed char stg[4][32 * OC];

    const int tid = threadIdx.x;
    const float sa = sc[s_a];
    if (tid < 128) lut[tid] = (signed char)(int)fq_q((float)tid * sa, sc[s_b]);
    for (int i = tid; i < NWB / 4; i += 128) wsm[i] = ((const int*)wq)[i];
    __syncthreads();

    const int bx = blockIdx.x, by = blockIdx.y, b = blockIdx.z;
    const signed char* wsb = (const signed char*)wsm;
    const float csa = __fdiv_rn(sc[s_in] * wsc[0], sa);

    if (by < SPLIT) {
        // ===================== IMMA path =====================
        const int w = tid >> 5, lane = tid & 31;
        const int g = lane >> 2, t = lane & 3;
        const int xw = bx * 128 + w * 32;
        float bva[NTL][2];
#pragma unroll
        for (int nt = 0; nt < NTL; nt++) {
            bva[nt][0] = __fdiv_rn(bias[nt * 8 + 2 * t], sa);
            bva[nt][1] = __fdiv_rn(bias[nt * 8 + 2 * t + 1], sa);
        }
#pragma unroll 1
        for (int yi = 0; yi < YB; yi++) {
            const int y = by * YB + yi;
            if (y >= Hout) break;
            int acc[2][NTL][4];
#pragma unroll
            for (int m = 0; m < 2; m++)
#pragma unroll
                for (int nt = 0; nt < NTL; nt++)
#pragma unroll
                    for (int k = 0; k < 4; k++) acc[m][nt][k] = 0;

            const signed char* base =
                in + ((long)b * BSi + (long)(y - PAD) * RSi + (xw - PAD)) * PXB;
#pragma unroll
            for (int c = 0; c < NCH; c++) {
                int t0, t1;
                long o0, o1;
                if (PXB == 16) {
                    t0 = 2 * c;
                    t1 = (2 * c + 1 < KK) ? 2 * c + 1 : 2 * c;
                    o0 = ((long)(t0 / K) * RSi + t0 % K) * 16;
                    o1 = ((long)(t1 / K) * RSi + t1 % K) * 16;
                } else {
                    t0 = c; t1 = c;
                    o0 = ((long)(c / K) * RSi + c % K) * 32;
                    o1 = o0 + 16;
                }
                const long osel = (t < 2) ? o0 : o1;
                const long boff = osel + 8 * (t & 1);
                uint2 A[2][2];
#pragma unroll
                for (int m = 0; m < 2; m++) {
                    const signed char* p = base + (m * 16 + g) * PXB + boff;
                    A[m][0] = *(const uint2*)p;
                    A[m][1] = *(const uint2*)(p + 8 * PXB);
                }
#pragma unroll
                for (int nt = 0; nt < NTL; nt++) {
                    uint2 B = *(const uint2*)(wsb + ((c * OC) + nt * 8 + g) * 32 + 8 * t);
#pragma unroll
                    for (int m = 0; m < 2; m++)
                        mma_k32(acc[m][nt], A[m][0].x, A[m][1].x, A[m][0].y, A[m][1].y,
                                B.x, B.y);
                }
            }
#pragma unroll
            for (int m = 0; m < 2; m++)
#pragma unroll
                for (int r = 0; r < 2; r++) {
                    const int pxl = m * 16 + r * 8 + g;
#pragma unroll
                    for (int nt = 0; nt < NTL; nt++) {
                        int c0 = __float2int_rn(fmaf((float)acc[m][nt][2 * r + 0], csa, bva[nt][0]));
                        int c1 = __float2int_rn(fmaf((float)acc[m][nt][2 * r + 1], csa, bva[nt][1]));
                        c0 = max(min(c0, 127), 0);
                        c1 = max(min(c1, 127), 0);
                        unsigned short pk = (unsigned short)((unsigned char)lut[c0] |
                                            ((unsigned)(unsigned char)lut[c1] << 8));
                        *(unsigned short*)(stg[w] + pxl * OC + nt * 8 + 2 * t) = pk;
                    }
                }
            __syncwarp();
#pragma unroll
            for (int i = lane; i < 2 * OC; i += 32) {
                const int pxl = (16 * i) / OC;
                const int x = xw + pxl;
                if (x < Wout)
                    *(uint4*)(out + ((long)b * BSo + (long)y * RSo + x) * OC + (16 * i) % OC) =
                        ((const uint4*)stg[w])[i];
            }
            __syncwarp();
        }
    } else {
        // ===================== dp4a path =====================
        constexpr int OCR = OC / 4;
        const int pxq = tid & 31, ocq = tid >> 5;
        const int oc0 = ocq * OCR;
        const int xd = bx * 128 + pxq * 4;
        float bvad[OCR];
#pragma unroll
        for (int j = 0; j < OCR; j++) bvad[j] = __fdiv_rn(bias[oc0 + j], sa);

#pragma unroll 1
        for (int yi = 0; yi < YB; yi++) {
            const int y = by * YB + yi;
            if (y >= Hout) break;
            int acc[4][OCR];
#pragma unroll
            for (int i = 0; i < 4; i++)
#pragma unroll
                for (int j = 0; j < OCR; j++) acc[i][j] = 0;

            const signed char* base =
                in + ((long)b * BSi + (long)(y - PAD) * RSi + (xd - PAD)) * PXB;
#pragma unroll 1
            for (int c = 0; c < NCH; c++) {
                int t0, t1;
                long o0, o1;
                if (PXB == 16) {
                    t0 = 2 * c;
                    t1 = (2 * c + 1 < KK) ? 2 * c + 1 : 2 * c;
                    o0 = ((long)(t0 / K) * RSi + t0 % K) * 16;
                    o1 = ((long)(t1 / K) * RSi + t1 % K) * 16;
                } else {
                    o0 = ((long)(c / K) * RSi + c % K) * 32;
                    o1 = o0 + 16;
                }
                const int* wrow = (const int*)wsb + (c * OC + oc0) * 8;
#pragma unroll
                for (int w8 = 0; w8 < 8; w8++) {
                    const long woff = ((w8 < 4) ? o0 : o1) + 4 * (w8 & 3);
                    int v[4];
#pragma unroll
                    for (int i = 0; i < 4; i++)
                        v[i] = *(const int*)(base + i * PXB + woff);
#pragma unroll
                    for (int j = 0; j < OCR; j++) {
                        const int wj = wrow[j * 8 + w8];
#pragma unroll
                        for (int i = 0; i < 4; i++) acc[i][j] = __dp4a(v[i], wj, acc[i][j]);
                    }
                }
            }
            // epilogue + direct store
#pragma unroll
            for (int i = 0; i < 4; i++) {
                const int x = xd + i;
                if (x < Wout) {
                    unsigned bytes[OCR / 4];
#pragma unroll
                    for (int q = 0; q < OCR / 4; q++) {
                        unsigned r = 0;
#pragma unroll
                        for (int k = 0; k < 4; k++) {
                            int j = q * 4 + k;
                            int cc = __float2int_rn(fmaf((float)acc[i][j], csa, bvad[j]));
                            r |= ((unsigned)(unsigned char)lut[max(min(cc, 127), 0)]) << (8 * k);
                        }
                        bytes[q] = r;
                    }
                    signed char* dst = out + ((long)b * BSo + (long)y * RSo + x) * OC + oc0;
                    if (OCR == 8) *(uint2*)dst = make_uint2(bytes[0], bytes[1]);
                    else *(unsigned*)dst = bytes[0];
                }
            }
        }
    }
}

// ---------------- maxpool ----------------
__global__ void pool_kernel(const float* __restrict__ sc) {
    __shared__ signed char lut[128];
    const int tid = threadIdx.x;
    if (tid < 128) lut[tid] = (signed char)(int)fq_q((float)tid * sc[6], sc[7]);
    __syncthreads();
    int idx = blockIdx.x * 256 + tid;
    if (idx >= 32 * 127 * 127 * 2) return;
    int half = idx & 1, p = idx >> 1;
    int x = p % 127, y = (p / 127) % 127, b = p / (127 * 127);
    const signed char* src = g_c3 + (((size_t)(b * 254 + 2 * y)) * 254 + 2 * x) * 32 + half * 16;
    int4 v00 = *(const int4*)src;
    int4 v01 = *(const int4*)(src + 32);
    int4 v10 = *(const int4*)(src + 254 * 32);
    int4 v11 = *(const int4*)(src + 254 * 32 + 32);
    int mw[4];
    mw[0] = __vmaxs4(__vmaxs4(v00.x, v01.x), __vmaxs4(v10.x, v11.x));
    mw[1] = __vmaxs4(__vmaxs4(v00.y, v01.y), __vmaxs4(v10.y, v11.y));
    mw[2] = __vmaxs4(__vmaxs4(v00.z, v01.z), __vmaxs4(v10.z, v11.z));
    mw[3] = __vmaxs4(__vmaxs4(v00.w, v01.w), __vmaxs4(v10.w, v11.w));
    unsigned rw[4];
#pragma unroll
    for (int ww = 0; ww < 4; ww++) {
        unsigned r = 0;
#pragma unroll
        for (int k = 0; k < 4; k++)
            r |= ((unsigned)(unsigned char)lut[sbyte(mw[ww], k)]) << (8 * k);
        rw[ww] = r;
    }
    *(uint4*)(g_pool + (((size_t)(b * 127 + y)) * 132 + x) * 32 + half * 16) =
        make_uint4(rw[0], rw[1], rw[2], rw[3]);
}

// ---------------- gap + fc ----------------
__global__ void gap_kernel(const float* __restrict__ sc) {
    __shared__ int red[256][16];
    const int b = blockIdx.x, tid = threadIdx.x;
    int acc[16];
#pragma unroll
    for (int k = 0; k < 16; k++) acc[k] = 0;
    const signed char* p = g_c4 + (size_t)b * 125 * 125 * 16;
    for (int i = tid; i < 125 * 125; i += 256) {
        int4 v = *(const int4*)(p + (size_t)i * 16);
        int wv[4] = {v.x, v.y, v.z, v.w};
#pragma unroll
        for (int j = 0; j < 4; j++)
#pragma unroll
            for (int k = 0; k < 4; k++) acc[j * 4 + k] += sbyte(wv[j], k);
    }
#pragma unroll
    for (int k = 0; k < 16; k++) red[tid][k] = acc[k];
    __syncthreads();
    for (int s = 128; s > 0; s >>= 1) {
        if (tid < s)
#pragma unroll
            for (int k = 0; k < 16; k++) red[tid][k] += red[tid + s][k];
        __syncthreads();
    }
    if (tid < 16)
        g_feat[b * 16 + tid] = fq(__fdiv_rn((float)red[0][tid] * sc[9], 15625.0f), sc[10]);
}

__global__ void fc_kernel(const float* __restrict__ bias, float* __restrict__ out) {
    int t = threadIdx.x;
    if (t >= 320) return;
    int b = t / 10, j = t % 10;
    float s = bias[j];
#pragma unroll
    for (int k = 0; k < 16; k++) s += g_feat[b * 16 + k] * g_qwc[k * 10 + j];
    out[b * 10 + j] = s;
}

// ---------------- launcher ----------------
extern "C" void kernel_launch(void* const* d_in, const int* in_sizes, int n_in,
                              void* d_out, int out_size) {
    const float* x  = (const float*)d_in[0];
    const float* w1 = (const float*)d_in[1];
    const float* b1 = (const float*)d_in[2];
    const float* w2 = (const float*)d_in[3];
    const float* b2 = (const float*)d_in[4];
    const float* w3 = (const float*)d_in[5];
    const float* b3 = (const float*)d_in[6];
    const float* w4 = (const float*)d_in[7];
    const float* b4 = (const float*)d_in[8];
    const float* wc = (const float*)d_in[9];
    const float* bc = (const float*)d_in[10];
    const float* sc = (const float*)d_in[11];
    float* out = (float*)d_out;

    signed char *pad16, *pad32, *poolb, *qw2, *qw3, *qw4, *c3, *c4;
    float* wsc;
    cudaGetSymbolAddress((void**)&pad16, g_pad16);
    cudaGetSymbolAddress((void**)&pad32, g_pad32);
    cudaGetSymbolAddress((void**)&poolb, g_pool);
    cudaGetSymbolAddress((void**)&qw2, g_qw2);
    cudaGetSymbolAddress((void**)&qw3, g_qw3);
    cudaGetSymbolAddress((void**)&qw4, g_qw4);
    cudaGetSymbolAddress((void**)&wsc, g_wscale);
    cudaGetSymbolAddress((void**)&c3, g_c3);
    cudaGetSymbolAddress((void**)&c4, g_c4);

    // 1. prep
    prep_kernel<<<2053 + 1031, 256>>>(x, w1, w2, w3, w4, wc, sc);

    // 2. conv1
    conv1_kernel<<<(32 * 254 * 254 + 255) / 256, 256>>>(b1, sc);

    // 3. conv2: 16->32 3x3 same, 5 paired chunks, hybrid split 22/10
    conv_hyb_kernel<16, 32, 3, 5, 8><<<dim3(2, 32, 32), 128>>>(
        pad16 + (size_t)ORG * 16, (long)HSP * WSP, WSP, 1, qw2, b2,
        pad32 + (size_t)ORG * 32, (long)HSP * WSP, WSP, 254, 254, sc, wsc + 1, 2, 3, 4, 22);

    // 4. conv3: 32->32 5x5 same, hybrid split 23/9   [profiled launch]
    conv_hyb_kernel<32, 32, 5, 25, 8><<<dim3(2, 32, 32), 128>>>(
        pad32 + (size_t)ORG * 32, (long)HSP * WSP, WSP, 2, qw3, b3,
        c3, (long)254 * 254, 254, 254, 254, sc, wsc + 2, 4, 5, 6, 23);

    // 5. maxpool
    pool_kernel<<<(32 * 127 * 127 * 2 + 255) / 256, 256>>>(sc);

    // 6. conv4: 32->16 3x3 valid, hybrid split 11/5
    conv_hyb_kernel<32, 16, 3, 9, 8><<<dim3(1, 16, 32), 128>>>(
        poolb, (long)127 * 132, 132, 0, qw4, b4,
        c4, (long)125 * 125, 125, 125, 125, sc, wsc + 3, 7, 8, 9, 11);

    // 7-8. gap + fc
    gap_kernel<<<32, 256>>>(sc);
    fc_kernel<<<1, 512>>>(bc, out);
}

// round 11
// speedup vs baseline: 4.0176x; 4.0176x over previous
#include <cuda_runtime.h>
#include <cstdint>

#define DI __device__ __forceinline__

DI float fq_q(float x, float s) {
    float q = rintf(__fdiv_rn(x, s));
    return fminf(fmaxf(q, -128.0f), 127.0f);
}
DI float fq(float x, float s) { return fq_q(x, s) * s; }
DI int sbyte(int w, int k) { return (int)((signed char)(w >> (8 * k))); }

#define WSP 264
#define HSP 260
#define ORG (3 * 264 + 3)

// ---------------- scratch ----------------
__device__ __align__(16) signed char g_pad16[(size_t)32 * HSP * WSP * 16];
__device__ __align__(16) signed char g_pad32[(size_t)32 * HSP * WSP * 32];
__device__ __align__(16) signed char g_c3[(size_t)32 * 254 * 254 * 32];
__device__ __align__(16) signed char g_pool[(size_t)32 * 127 * 132 * 32];
__device__ __align__(16) signed char g_c4[(size_t)32 * 125 * 125 * 16];
__device__ __align__(16) signed char g_in0[(size_t)32 * 256 * 256];
__device__ __align__(16) int g_qw1[9 * 16];
__device__ __align__(16) signed char g_qw2[5 * 32 * 32];    // [chunk][oc][32B] paired taps
__device__ __align__(16) signed char g_qw3[25 * 32 * 32];   // [tap][oc][ic]
__device__ __align__(16) signed char g_qw4[9 * 16 * 32];    // [tap][oc][ic]
__device__ float g_qwc[160], g_wscale[8], g_feat[512];

DI void mma_k32(int d[4], unsigned a0, unsigned a1, unsigned a2, unsigned a3,
                unsigned b0, unsigned b1) {
    asm volatile(
        "mma.sync.aligned.m16n8k32.row.col.s32.s8.s8.s32 "
        "{%0,%1,%2,%3}, {%4,%5,%6,%7}, {%8,%9}, {%0,%1,%2,%3};\n"
        : "+r"(d[0]), "+r"(d[1]), "+r"(d[2]), "+r"(d[3])
        : "r"(a0), "r"(a1), "r"(a2), "r"(a3), "r"(b0), "r"(b1));
}

// ---------------- prep ----------------
DI float bmax(const float* w, int n, float* red) {
    float m = 0.0f;
    for (int i = threadIdx.x; i < n; i += 256) m = fmaxf(m, fabsf(w[i]));
    red[threadIdx.x] = m;
    __syncthreads();
    for (int s = 128; s > 0; s >>= 1) {
        if (threadIdx.x < s) red[threadIdx.x] = fmaxf(red[threadIdx.x], red[threadIdx.x + s]);
        __syncthreads();
    }
    return red[0];
}

__global__ void prep_kernel(const float* __restrict__ x, const float* __restrict__ w1,
                            const float* __restrict__ w2, const float* __restrict__ w3,
                            const float* __restrict__ w4, const float* __restrict__ wc,
                            const float* __restrict__ sc) {
    __shared__ float red[256];
    const int blk = blockIdx.x, tid = threadIdx.x;
    if (blk < 2048) {
        int i = blk * 256 + tid;
        float4 v = ((const float4*)x)[i];
        float inv = __frcp_rn(sc[0]);
        int c0 = max(min(__float2int_rn(v.x * inv), 127), -128);
        int c1 = max(min(__float2int_rn(v.y * inv), 127), -128);
        int c2 = max(min(__float2int_rn(v.z * inv), 127), -128);
        int c3 = max(min(__float2int_rn(v.w * inv), 127), -128);
        ((int*)g_in0)[i] = (c0 & 0xFF) | ((c1 & 0xFF) << 8) | ((c2 & 0xFF) << 16) |
                           ((c3 & 0xFF) << 24);
    } else if (blk == 2048) {
        float s = __fdiv_rn(bmax(w1, 144, red), 127.0f);
        if (tid == 0) g_wscale[0] = s;
        for (int i = tid; i < 144; i += 256) g_qw1[(i % 9) * 16 + i / 9] = (int)fq_q(w1[i], s);
    } else if (blk == 2049) {  // conv2: 5 paired chunks [c][oc][32B]
        float s = __fdiv_rn(bmax(w2, 4608, red), 127.0f);
        if (tid == 0) g_wscale[1] = s;
        for (int i = tid; i < 5120; i += 256) {
            int j = i & 31, oc = (i >> 5) & 31, c = i >> 10;
            int tap = 2 * c + (j >= 16), ic = j & 15;
            signed char v = 0;
            if (tap < 9)
                v = (signed char)(int)fq_q(w2[((oc * 16 + ic) * 3 + tap / 3) * 3 + tap % 3], s);
            g_qw2[i] = v;
        }
    } else if (blk == 2050) {
        float s = __fdiv_rn(bmax(w3, 25600, red), 127.0f);
        if (tid == 0) g_wscale[2] = s;
        for (int i = tid; i < 25600; i += 256) {
            int ic = i & 31, oc = (i >> 5) & 31, tap = i >> 10;
            g_qw3[i] = (signed char)(int)fq_q(w3[((oc * 32 + ic) * 5 + tap / 5) * 5 + tap % 5], s);
        }
    } else if (blk == 2051) {
        float s = __fdiv_rn(bmax(w4, 4608, red), 127.0f);
        if (tid == 0) g_wscale[3] = s;
        for (int i = tid; i < 4608; i += 256) {
            int ic = i & 31, oc = (i >> 5) & 15, tap = i >> 9;
            g_qw4[i] = (signed char)(int)fq_q(w4[((oc * 32 + ic) * 3 + tap / 3) * 3 + tap % 3], s);
        }
    } else if (blk == 2052) {
        float s = __fdiv_rn(bmax(wc, 160, red), 127.0f);
        for (int i = tid; i < 160; i += 256) g_qwc[(i % 16) * 10 + i / 16] = fq_q(wc[i], s) * s;
    } else {
        int idx = (blk - 2053) * 256 + tid;
        const int ITEMS = 32 * 4124;
        int which = idx >= ITEMS;
        if (which) idx -= ITEMS;
        int b = idx / 4124, i = idx % 4124, pr, pc;
        if (i < 1584) { pc = i % 264; int r = i / 264; pr = (r < 3) ? r : 254 + r; }
        else { int j = i - 1584; pr = 3 + j / 10; int c = j % 10; pc = (c < 3) ? c : 254 + c; }
        size_t px = ((size_t)b * HSP + pr) * WSP + pc;
        uint4 z = make_uint4(0, 0, 0, 0);
        if (!which) {
            *(uint4*)(g_pad16 + px * 16) = z;
        } else {
            uint4* d = (uint4*)(g_pad32 + px * 32);
            d[0] = z; d[1] = z;
        }
    }
}

// ---------------- conv1 ----------------
__global__ void __launch_bounds__(256) conv1_kernel(const float* __restrict__ bias,
                                                    const float* __restrict__ sc) {
    __shared__ int wsm[144];
    __shared__ signed char lut[128];
    __shared__ float bsm[16];
    const int tid = threadIdx.x;
    const float sa = sc[1], sb = sc[2];
    if (tid < 128) lut[tid] = (signed char)(int)fq_q((float)tid * sa, sb);
    if (tid < 144) wsm[tid] = g_qw1[tid];
    if (tid >= 144 && tid < 160) bsm[tid - 144] = bias[tid - 144];
    __syncthreads();
    int idx = blockIdx.x * 256 + tid;
    if (idx >= 32 * 254 * 254) return;
    int x = idx % 254, y = (idx / 254) % 254, b = idx / (254 * 254);
    const signed char* base = g_in0 + (size_t)b * 65536;
    int v[9];
#pragma unroll
    for (int ky = 0; ky < 3; ky++)
#pragma unroll
        for (int kx = 0; kx < 3; kx++)
            v[ky * 3 + kx] = (int)base[(size_t)(y + ky) * 256 + x + kx];
    int acc[16];
#pragma unroll
    for (int j = 0; j < 16; j++) acc[j] = 0;
#pragma unroll
    for (int t = 0; t < 9; t++)
#pragma unroll
        for (int j = 0; j < 16; j++) acc[j] += v[t] * wsm[t * 16 + j];
    const float csa = __fdiv_rn(sc[0] * g_wscale[0], sa);
    unsigned wds[4];
#pragma unroll
    for (int g = 0; g < 4; g++) {
        unsigned wd = 0;
#pragma unroll
        for (int k = 0; k < 4; k++) {
            int j = g * 4 + k;
            int c = __float2int_rn(fmaf((float)acc[j], csa, __fdiv_rn(bsm[j], sa)));
            wd |= ((unsigned)(unsigned char)lut[max(min(c, 127), 0)]) << (8 * k);
        }
        wds[g] = wd;
    }
    *(uint4*)(g_pad16 + (((size_t)b * HSP + y + 3) * WSP + x + 3) * 16) =
        make_uint4(wds[0], wds[1], wds[2], wds[3]);
}

// ---------------- hybrid conv: y-groups < SPLIT run IMMA, rest run dp4a ----------------
template <int PXB, int OC, int K, int NCH, int YB>
__global__ void __launch_bounds__(128) conv_hyb_kernel(
    const signed char* __restrict__ in, long BSi, int RSi, int PAD,
    const signed char* __restrict__ wq, const float* __restrict__ bias,
    signed char* __restrict__ out, long BSo, int RSo, int Wout, int Hout,
    const float* __restrict__ sc, const float* __restrict__ wsc,
    int s_in, int s_a, int s_b, int SPLIT) {
    constexpr int NTL = OC / 8;
    constexpr int KK = K * K;
    constexpr int NWB = NCH * OC * 32;

    __shared__ int wsm[NWB / 4];
    __shared__ signed char lut[128];
    __shared__ float s_bva[OC];
    __shared__ __align__(16) signed char stg[4][32 * OC];

    const int tid = threadIdx.x;
    const float sa = sc[s_a];
    if (tid < 128) lut[tid] = (signed char)(int)fq_q((float)tid * sa, sc[s_b]);
    if (tid < OC) s_bva[tid] = __fdiv_rn(bias[tid], sa);
    for (int i = tid; i < NWB / 4; i += 128) wsm[i] = ((const int*)wq)[i];
    __syncthreads();

    const int bx = blockIdx.x, by = blockIdx.y, b = blockIdx.z;
    const signed char* wsb = (const signed char*)wsm;
    const float csa = __fdiv_rn(sc[s_in] * wsc[0], sa);

    if (by < SPLIT) {
        // ===================== IMMA path (unchanged, validated) =====================
        const int w = tid >> 5, lane = tid & 31;
        const int g = lane >> 2, t = lane & 3;
        const int xw = bx * 128 + w * 32;
        float bva[NTL][2];
#pragma unroll
        for (int nt = 0; nt < NTL; nt++) {
            bva[nt][0] = __fdiv_rn(bias[nt * 8 + 2 * t], sa);
            bva[nt][1] = __fdiv_rn(bias[nt * 8 + 2 * t + 1], sa);
        }
#pragma unroll 1
        for (int yi = 0; yi < YB; yi++) {
            const int y = by * YB + yi;
            if (y >= Hout) break;
            int acc[2][NTL][4];
#pragma unroll
            for (int m = 0; m < 2; m++)
#pragma unroll
                for (int nt = 0; nt < NTL; nt++)
#pragma unroll
                    for (int k = 0; k < 4; k++) acc[m][nt][k] = 0;

            const signed char* base =
                in + ((long)b * BSi + (long)(y - PAD) * RSi + (xw - PAD)) * PXB;
#pragma unroll
            for (int c = 0; c < NCH; c++) {
                int t0, t1;
                long o0, o1;
                if (PXB == 16) {
                    t0 = 2 * c;
                    t1 = (2 * c + 1 < KK) ? 2 * c + 1 : 2 * c;
                    o0 = ((long)(t0 / K) * RSi + t0 % K) * 16;
                    o1 = ((long)(t1 / K) * RSi + t1 % K) * 16;
                } else {
                    o0 = ((long)(c / K) * RSi + c % K) * 32;
                    o1 = o0 + 16;
                }
                const long osel = (t < 2) ? o0 : o1;
                const long boff = osel + 8 * (t & 1);
                uint2 A[2][2];
#pragma unroll
                for (int m = 0; m < 2; m++) {
                    const signed char* p = base + (m * 16 + g) * PXB + boff;
                    A[m][0] = *(const uint2*)p;
                    A[m][1] = *(const uint2*)(p + 8 * PXB);
                }
#pragma unroll
                for (int nt = 0; nt < NTL; nt++) {
                    uint2 B = *(const uint2*)(wsb + ((c * OC) + nt * 8 + g) * 32 + 8 * t);
#pragma unroll
                    for (int m = 0; m < 2; m++)
                        mma_k32(acc[m][nt], A[m][0].x, A[m][1].x, A[m][0].y, A[m][1].y,
                                B.x, B.y);
                }
            }
#pragma unroll
            for (int m = 0; m < 2; m++)
#pragma unroll
                for (int r = 0; r < 2; r++) {
                    const int pxl = m * 16 + r * 8 + g;
#pragma unroll
                    for (int nt = 0; nt < NTL; nt++) {
                        int c0 = __float2int_rn(fmaf((float)acc[m][nt][2 * r + 0], csa, bva[nt][0]));
                        int c1 = __float2int_rn(fmaf((float)acc[m][nt][2 * r + 1], csa, bva[nt][1]));
                        c0 = max(min(c0, 127), 0);
                        c1 = max(min(c1, 127), 0);
                        unsigned short pk = (unsigned short)((unsigned char)lut[c0] |
                                            ((unsigned)(unsigned char)lut[c1] << 8));
                        *(unsigned short*)(stg[w] + pxl * OC + nt * 8 + 2 * t) = pk;
                    }
                }
            __syncwarp();
#pragma unroll
            for (int i = lane; i < 2 * OC; i += 32) {
                const int pxl = (16 * i) / OC;
                const int x = xw + pxl;
                if (x < Wout)
                    *(uint4*)(out + ((long)b * BSo + (long)y * RSo + x) * OC + (16 * i) % OC) =
                        ((const uint4*)stg[w])[i];
            }
            __syncwarp();
        }
    } else {
        // ===================== dp4a path: thread = pixel, coalesced LDG.128 =====================
        const int xd = bx * 128 + tid;
#pragma unroll 1
        for (int yi = 0; yi < YB; yi++) {
            const int y = by * YB + yi;
            if (y >= Hout) break;
            int acc[OC];
#pragma unroll
            for (int j = 0; j < OC; j++) acc[j] = 0;

            const signed char* base =
                in + ((long)b * BSi + (long)(y - PAD) * RSi + (xd - PAD)) * PXB;
#pragma unroll 1
            for (int c = 0; c < NCH; c++) {
                long o0, o1;
                if (PXB == 16) {
                    int t0 = 2 * c;
                    int t1 = (2 * c + 1 < KK) ? 2 * c + 1 : 2 * c;
                    o0 = ((long)(t0 / K) * RSi + t0 % K) * 16;
                    o1 = ((long)(t1 / K) * RSi + t1 % K) * 16;
                } else {
                    o0 = ((long)(c / K) * RSi + c % K) * 32;
                    o1 = o0 + 16;
                }
                uint4 va = *(const uint4*)(base + o0);
                uint4 vb = *(const uint4*)(base + o1);
                int v[8] = {(int)va.x, (int)va.y, (int)va.z, (int)va.w,
                            (int)vb.x, (int)vb.y, (int)vb.z, (int)vb.w};
                const int* wrow = (const int*)wsb + c * OC * 8;
#pragma unroll
                for (int j = 0; j < OC; j++) {
                    int4 w0 = ((const int4*)(wrow + j * 8))[0];
                    int4 w1 = ((const int4*)(wrow + j * 8))[1];
                    int a = acc[j];
                    a = __dp4a(v[0], w0.x, a);
                    a = __dp4a(v[1], w0.y, a);
                    a = __dp4a(v[2], w0.z, a);
                    a = __dp4a(v[3], w0.w, a);
                    a = __dp4a(v[4], w1.x, a);
                    a = __dp4a(v[5], w1.y, a);
                    a = __dp4a(v[6], w1.z, a);
                    a = __dp4a(v[7], w1.w, a);
                    acc[j] = a;
                }
            }
            if (xd < Wout) {
                unsigned bytes[OC / 4];
#pragma unroll
                for (int q = 0; q < OC / 4; q++) {
                    unsigned r = 0;
#pragma unroll
                    for (int k = 0; k < 4; k++) {
                        int j = q * 4 + k;
                        int cc = __float2int_rn(fmaf((float)acc[j], csa, s_bva[j]));
                        r |= ((unsigned)(unsigned char)lut[max(min(cc, 127), 0)]) << (8 * k);
                    }
                    bytes[q] = r;
                }
                signed char* dst = out + ((long)b * BSo + (long)y * RSo + xd) * OC;
#pragma unroll
                for (int q = 0; q < OC / 16; q++)
                    ((uint4*)dst)[q] = ((const uint4*)bytes)[q];
            }
        }
    }
}

// ---------------- maxpool ----------------
__global__ void pool_kernel(const float* __restrict__ sc) {
    __shared__ signed char lut[128];
    const int tid = threadIdx.x;
    if (tid < 128) lut[tid] = (signed char)(int)fq_q((float)tid * sc[6], sc[7]);
    __syncthreads();
    int idx = blockIdx.x * 256 + tid;
    if (idx >= 32 * 127 * 127 * 2) return;
    int half = idx & 1, p = idx >> 1;
    int x = p % 127, y = (p / 127) % 127, b = p / (127 * 127);
    const signed char* src = g_c3 + (((size_t)(b * 254 + 2 * y)) * 254 + 2 * x) * 32 + half * 16;
    int4 v00 = *(const int4*)src;
    int4 v01 = *(const int4*)(src + 32);
    int4 v10 = *(const int4*)(src + 254 * 32);
    int4 v11 = *(const int4*)(src + 254 * 32 + 32);
    int mw[4];
    mw[0] = __vmaxs4(__vmaxs4(v00.x, v01.x), __vmaxs4(v10.x, v11.x));
    mw[1] = __vmaxs4(__vmaxs4(v00.y, v01.y), __vmaxs4(v10.y, v11.y));
    mw[2] = __vmaxs4(__vmaxs4(v00.z, v01.z), __vmaxs4(v10.z, v11.z));
    mw[3] = __vmaxs4(__vmaxs4(v00.w, v01.w), __vmaxs4(v10.w, v11.w));
    unsigned rw[4];
#pragma unroll
    for (int ww = 0; ww < 4; ww++) {
        unsigned r = 0;
#pragma unroll
        for (int k = 0; k < 4; k++)
            r |= ((unsigned)(unsigned char)lut[sbyte(mw[ww], k)]) << (8 * k);
        rw[ww] = r;
    }
    *(uint4*)(g_pool + (((size_t)(b * 127 + y)) * 132 + x) * 32 + half * 16) =
        make_uint4(rw[0], rw[1], rw[2], rw[3]);
}

// ---------------- gap + fc ----------------
__global__ void gap_kernel(const float* __restrict__ sc) {
    __shared__ int red[256][16];
    const int b = blockIdx.x, tid = threadIdx.x;
    int acc[16];
#pragma unroll
    for (int k = 0; k < 16; k++) acc[k] = 0;
    const signed char* p = g_c4 + (size_t)b * 125 * 125 * 16;
    for (int i = tid; i < 125 * 125; i += 256) {
        int4 v = *(const int4*)(p + (size_t)i * 16);
        int wv[4] = {v.x, v.y, v.z, v.w};
#pragma unroll
        for (int j = 0; j < 4; j++)
#pragma unroll
            for (int k = 0; k < 4; k++) acc[j * 4 + k] += sbyte(wv[j], k);
    }
#pragma unroll
    for (int k = 0; k < 16; k++) red[tid][k] = acc[k];
    __syncthreads();
    for (int s = 128; s > 0; s >>= 1) {
        if (tid < s)
#pragma unroll
            for (int k = 0; k < 16; k++) red[tid][k] += red[tid + s][k];
        __syncthreads();
    }
    if (tid < 16)
        g_feat[b * 16 + tid] = fq(__fdiv_rn((float)red[0][tid] * sc[9], 15625.0f), sc[10]);
}

__global__ void fc_kernel(const float* __restrict__ bias, float* __restrict__ out) {
    int t = threadIdx.x;
    if (t >= 320) return;
    int b = t / 10, j = t % 10;
    float s = bias[j];
#pragma unroll
    for (int k = 0; k < 16; k++) s += g_feat[b * 16 + k] * g_qwc[k * 10 + j];
    out[b * 10 + j] = s;
}

// ---------------- launcher ----------------
extern "C" void kernel_launch(void* const* d_in, const int* in_sizes, int n_in,
                              void* d_out, int out_size) {
    const float* x  = (const float*)d_in[0];
    const float* w1 = (const float*)d_in[1];
    const float* b1 = (const float*)d_in[2];
    const float* w2 = (const float*)d_in[3];
    const float* b2 = (const float*)d_in[4];
    const float* w3 = (const float*)d_in[5];
    const float* b3 = (const float*)d_in[6];
    const float* w4 = (const float*)d_in[7];
    const float* b4 = (const float*)d_in[8];
    const float* wc = (const float*)d_in[9];
    const float* bc = (const float*)d_in[10];
    const float* sc = (const float*)d_in[11];
    float* out = (float*)d_out;

    signed char *pad16, *pad32, *poolb, *qw2, *qw3, *qw4, *c3, *c4;
    float* wsc;
    cudaGetSymbolAddress((void**)&pad16, g_pad16);
    cudaGetSymbolAddress((void**)&pad32, g_pad32);
    cudaGetSymbolAddress((void**)&poolb, g_pool);
    cudaGetSymbolAddress((void**)&qw2, g_qw2);
    cudaGetSymbolAddress((void**)&qw3, g_qw3);
    cudaGetSymbolAddress((void**)&qw4, g_qw4);
    cudaGetSymbolAddress((void**)&wsc, g_wscale);
    cudaGetSymbolAddress((void**)&c3, g_c3);
    cudaGetSymbolAddress((void**)&c4, g_c4);

    // 1. prep
    prep_kernel<<<2053 + 1031, 256>>>(x, w1, w2, w3, w4, wc, sc);

    // 2. conv1
    conv1_kernel<<<(32 * 254 * 254 + 255) / 256, 256>>>(b1, sc);

    // 3. conv2: 16->32 3x3 same, 5 paired chunks, hybrid split 18 IMMA / 14 dp4a
    conv_hyb_kernel<16, 32, 3, 5, 8><<<dim3(2, 32, 32), 128>>>(
        pad16 + (size_t)ORG * 16, (long)HSP * WSP, WSP, 1, qw2, b2,
        pad32 + (size_t)ORG * 32, (long)HSP * WSP, WSP, 254, 254, sc, wsc + 1, 2, 3, 4, 18);

    // 4. conv3: 32->32 5x5 same, hybrid split 18/14   [profiled launch]
    conv_hyb_kernel<32, 32, 5, 25, 8><<<dim3(2, 32, 32), 128>>>(
        pad32 + (size_t)ORG * 32, (long)HSP * WSP, WSP, 2, qw3, b3,
        c3, (long)254 * 254, 254, 254, 254, sc, wsc + 2, 4, 5, 6, 18);

    // 5. maxpool
    pool_kernel<<<(32 * 127 * 127 * 2 + 255) / 256, 256>>>(sc);

    // 6. conv4: 32->16 3x3 valid, hybrid split 9/7
    conv_hyb_kernel<32, 16, 3, 9, 8><<<dim3(1, 16, 32), 128>>>(
        poolb, (long)127 * 132, 132, 0, qw4, b4,
        c4, (long)125 * 125, 125, 125, 125, sc, wsc + 3, 7, 8, 9, 9);

    // 7-8. gap + fc
    gap_kernel<<<32, 256>>>(sc);
    fc_kernel<<<1, 512>>>(bc, out);
}

// round 12
// speedup vs baseline: 4.1590x; 1.0352x over previous
#include <cuda_runtime.h>
#include <cstdint>

#define DI __device__ __forceinline__

DI float fq_q(float x, float s) {
    float q = rintf(__fdiv_rn(x, s));
    return fminf(fmaxf(q, -128.0f), 127.0f);
}
DI float fq(float x, float s) { return fq_q(x, s) * s; }
DI int sbyte(int w, int k) { return (int)((signed char)(w >> (8 * k))); }

#define WSP 264
#define HSP 260
#define ORG (3 * 264 + 3)

// ---------------- scratch ----------------
__device__ __align__(16) signed char g_pad16[(size_t)32 * HSP * WSP * 16];
__device__ __align__(16) signed char g_pad32[(size_t)32 * HSP * WSP * 32];
__device__ __align__(16) signed char g_c3[(size_t)32 * 254 * 254 * 32];
__device__ __align__(16) signed char g_pool[(size_t)32 * 127 * 132 * 32];
__device__ __align__(16) signed char g_c4[(size_t)32 * 125 * 125 * 16];
__device__ __align__(16) signed char g_in0[(size_t)32 * 256 * 256];
__device__ __align__(16) int g_qw1[9 * 16];
__device__ __align__(16) signed char g_qw2[5 * 32 * 32];    // [chunk][oc][32B] paired taps
__device__ __align__(16) signed char g_qw3[25 * 32 * 32];   // [tap][oc][ic]
__device__ __align__(16) signed char g_qw4[9 * 16 * 32];    // [tap][oc][ic]
__device__ float g_qwc[160], g_wscale[8], g_feat[512];

DI void mma_k32(int d[4], unsigned a0, unsigned a1, unsigned a2, unsigned a3,
                unsigned b0, unsigned b1) {
    asm volatile(
        "mma.sync.aligned.m16n8k32.row.col.s32.s8.s8.s32 "
        "{%0,%1,%2,%3}, {%4,%5,%6,%7}, {%8,%9}, {%0,%1,%2,%3};\n"
        : "+r"(d[0]), "+r"(d[1]), "+r"(d[2]), "+r"(d[3])
        : "r"(a0), "r"(a1), "r"(a2), "r"(a3), "r"(b0), "r"(b1));
}

// ---------------- prep ----------------
DI float bmax(const float* w, int n, float* red) {
    float m = 0.0f;
    for (int i = threadIdx.x; i < n; i += 256) m = fmaxf(m, fabsf(w[i]));
    red[threadIdx.x] = m;
    __syncthreads();
    for (int s = 128; s > 0; s >>= 1) {
        if (threadIdx.x < s) red[threadIdx.x] = fmaxf(red[threadIdx.x], red[threadIdx.x + s]);
        __syncthreads();
    }
    return red[0];
}

__global__ void prep_kernel(const float* __restrict__ x, const float* __restrict__ w1,
                            const float* __restrict__ w2, const float* __restrict__ w3,
                            const float* __restrict__ w4, const float* __restrict__ wc,
                            const float* __restrict__ sc) {
    __shared__ float red[256];
    const int blk = blockIdx.x, tid = threadIdx.x;
    if (blk < 2048) {
        int i = blk * 256 + tid;
        float4 v = ((const float4*)x)[i];
        float inv = __frcp_rn(sc[0]);
        int c0 = max(min(__float2int_rn(v.x * inv), 127), -128);
        int c1 = max(min(__float2int_rn(v.y * inv), 127), -128);
        int c2 = max(min(__float2int_rn(v.z * inv), 127), -128);
        int c3 = max(min(__float2int_rn(v.w * inv), 127), -128);
        ((int*)g_in0)[i] = (c0 & 0xFF) | ((c1 & 0xFF) << 8) | ((c2 & 0xFF) << 16) |
                           ((c3 & 0xFF) << 24);
    } else if (blk == 2048) {
        float s = __fdiv_rn(bmax(w1, 144, red), 127.0f);
        if (tid == 0) g_wscale[0] = s;
        for (int i = tid; i < 144; i += 256) g_qw1[(i % 9) * 16 + i / 9] = (int)fq_q(w1[i], s);
    } else if (blk == 2049) {  // conv2: 5 paired chunks [c][oc][32B]
        float s = __fdiv_rn(bmax(w2, 4608, red), 127.0f);
        if (tid == 0) g_wscale[1] = s;
        for (int i = tid; i < 5120; i += 256) {
            int j = i & 31, oc = (i >> 5) & 31, c = i >> 10;
            int tap = 2 * c + (j >= 16), ic = j & 15;
            signed char v = 0;
            if (tap < 9)
                v = (signed char)(int)fq_q(w2[((oc * 16 + ic) * 3 + tap / 3) * 3 + tap % 3], s);
            g_qw2[i] = v;
        }
    } else if (blk == 2050) {
        float s = __fdiv_rn(bmax(w3, 25600, red), 127.0f);
        if (tid == 0) g_wscale[2] = s;
        for (int i = tid; i < 25600; i += 256) {
            int ic = i & 31, oc = (i >> 5) & 31, tap = i >> 10;
            g_qw3[i] = (signed char)(int)fq_q(w3[((oc * 32 + ic) * 5 + tap / 5) * 5 + tap % 5], s);
        }
    } else if (blk == 2051) {
        float s = __fdiv_rn(bmax(w4, 4608, red), 127.0f);
        if (tid == 0) g_wscale[3] = s;
        for (int i = tid; i < 4608; i += 256) {
            int ic = i & 31, oc = (i >> 5) & 15, tap = i >> 9;
            g_qw4[i] = (signed char)(int)fq_q(w4[((oc * 32 + ic) * 3 + tap / 3) * 3 + tap % 3], s);
        }
    } else if (blk == 2052) {
        float s = __fdiv_rn(bmax(wc, 160, red), 127.0f);
        for (int i = tid; i < 160; i += 256) g_qwc[(i % 16) * 10 + i / 16] = fq_q(wc[i], s) * s;
    } else {
        int idx = (blk - 2053) * 256 + tid;
        const int ITEMS = 32 * 4124;
        int which = idx >= ITEMS;
        if (which) idx -= ITEMS;
        int b = idx / 4124, i = idx % 4124, pr, pc;
        if (i < 1584) { pc = i % 264; int r = i / 264; pr = (r < 3) ? r : 254 + r; }
        else { int j = i - 1584; pr = 3 + j / 10; int c = j % 10; pc = (c < 3) ? c : 254 + c; }
        size_t px = ((size_t)b * HSP + pr) * WSP + pc;
        uint4 z = make_uint4(0, 0, 0, 0);
        if (!which) {
            *(uint4*)(g_pad16 + px * 16) = z;
        } else {
            uint4* d = (uint4*)(g_pad32 + px * 32);
            d[0] = z; d[1] = z;
        }
    }
}

// ---------------- conv1 ----------------
__global__ void __launch_bounds__(256) conv1_kernel(const float* __restrict__ bias,
                                                    const float* __restrict__ sc) {
    __shared__ int wsm[144];
    __shared__ signed char lut[128];
    __shared__ float bsm[16];
    const int tid = threadIdx.x;
    const float sa = sc[1], sb = sc[2];
    if (tid < 128) lut[tid] = (signed char)(int)fq_q((float)tid * sa, sb);
    if (tid < 144) wsm[tid] = g_qw1[tid];
    if (tid >= 144 && tid < 160) bsm[tid - 144] = bias[tid - 144];
    __syncthreads();
    int idx = blockIdx.x * 256 + tid;
    if (idx >= 32 * 254 * 254) return;
    int x = idx % 254, y = (idx / 254) % 254, b = idx / (254 * 254);
    const signed char* base = g_in0 + (size_t)b * 65536;
    int v[9];
#pragma unroll
    for (int ky = 0; ky < 3; ky++)
#pragma unroll
        for (int kx = 0; kx < 3; kx++)
            v[ky * 3 + kx] = (int)base[(size_t)(y + ky) * 256 + x + kx];
    int acc[16];
#pragma unroll
    for (int j = 0; j < 16; j++) acc[j] = 0;
#pragma unroll
    for (int t = 0; t < 9; t++)
#pragma unroll
        for (int j = 0; j < 16; j++) acc[j] += v[t] * wsm[t * 16 + j];
    const float csa = __fdiv_rn(sc[0] * g_wscale[0], sa);
    unsigned wds[4];
#pragma unroll
    for (int g = 0; g < 4; g++) {
        unsigned wd = 0;
#pragma unroll
        for (int k = 0; k < 4; k++) {
            int j = g * 4 + k;
            int c = __float2int_rn(fmaf((float)acc[j], csa, __fdiv_rn(bsm[j], sa)));
            wd |= ((unsigned)(unsigned char)lut[max(min(c, 127), 0)]) << (8 * k);
        }
        wds[g] = wd;
    }
    *(uint4*)(g_pad16 + (((size_t)b * HSP + y + 3) * WSP + x + 3) * 16) =
        make_uint4(wds[0], wds[1], wds[2], wds[3]);
}

// ---------------- hybrid conv: y-groups < SPLIT run IMMA, rest run dp4a ----------------
template <int PXB, int OC, int K, int NCH, int YB>
__global__ void __launch_bounds__(128) conv_hyb_kernel(
    const signed char* __restrict__ in, long BSi, int RSi, int PAD,
    const signed char* __restrict__ wq, const float* __restrict__ bias,
    signed char* __restrict__ out, long BSo, int RSo, int Wout, int Hout,
    const float* __restrict__ sc, const float* __restrict__ wsc,
    int s_in, int s_a, int s_b, int SPLIT) {
    constexpr int NTL = OC / 8;
    constexpr int KK = K * K;
    constexpr int NWB = NCH * OC * 32;

    __shared__ int wsm[NWB / 4];
    __shared__ signed char lut[128];
    __shared__ float s_bva[OC];
    __shared__ int s_off[NCH * 2];
    __shared__ __align__(16) signed char stg[4][32 * OC];

    const int tid = threadIdx.x;
    const float sa = sc[s_a];
    if (tid < 128) lut[tid] = (signed char)(int)fq_q((float)tid * sa, sc[s_b]);
    if (tid < OC) s_bva[tid] = __fdiv_rn(bias[tid], sa);
    if (tid < NCH) {  // offset table for dp4a path
        int o0, o1;
        if (PXB == 16) {
            int t0 = 2 * tid;
            int t1 = (2 * tid + 1 < KK) ? 2 * tid + 1 : 2 * tid;
            o0 = ((t0 / K) * RSi + t0 % K) * 16;
            o1 = ((t1 / K) * RSi + t1 % K) * 16;
        } else {
            o0 = ((tid / K) * RSi + tid % K) * 32;
            o1 = o0 + 16;
        }
        s_off[2 * tid] = o0;
        s_off[2 * tid + 1] = o1;
    }
    for (int i = tid; i < NWB / 4; i += 128) wsm[i] = ((const int*)wq)[i];
    __syncthreads();

    const int bx = blockIdx.x, by = blockIdx.y, b = blockIdx.z;
    const signed char* wsb = (const signed char*)wsm;
    const float csa = __fdiv_rn(sc[s_in] * wsc[0], sa);

    if (by < SPLIT) {
        // ===================== IMMA path (unchanged, validated) =====================
        const int w = tid >> 5, lane = tid & 31;
        const int g = lane >> 2, t = lane & 3;
        const int xw = bx * 128 + w * 32;
        float bva[NTL][2];
#pragma unroll
        for (int nt = 0; nt < NTL; nt++) {
            bva[nt][0] = __fdiv_rn(bias[nt * 8 + 2 * t], sa);
            bva[nt][1] = __fdiv_rn(bias[nt * 8 + 2 * t + 1], sa);
        }
#pragma unroll 1
        for (int yi = 0; yi < YB; yi++) {
            const int y = by * YB + yi;
            if (y >= Hout) break;
            int acc[2][NTL][4];
#pragma unroll
            for (int m = 0; m < 2; m++)
#pragma unroll
                for (int nt = 0; nt < NTL; nt++)
#pragma unroll
                    for (int k = 0; k < 4; k++) acc[m][nt][k] = 0;

            const signed char* base =
                in + ((long)b * BSi + (long)(y - PAD) * RSi + (xw - PAD)) * PXB;
#pragma unroll
            for (int c = 0; c < NCH; c++) {
                int t0, t1;
                long o0, o1;
                if (PXB == 16) {
                    t0 = 2 * c;
                    t1 = (2 * c + 1 < KK) ? 2 * c + 1 : 2 * c;
                    o0 = ((long)(t0 / K) * RSi + t0 % K) * 16;
                    o1 = ((long)(t1 / K) * RSi + t1 % K) * 16;
                } else {
                    o0 = ((long)(c / K) * RSi + c % K) * 32;
                    o1 = o0 + 16;
                }
                const long osel = (t < 2) ? o0 : o1;
                const long boff = osel + 8 * (t & 1);
                uint2 A[2][2];
#pragma unroll
                for (int m = 0; m < 2; m++) {
                    const signed char* p = base + (m * 16 + g) * PXB + boff;
                    A[m][0] = *(const uint2*)p;
                    A[m][1] = *(const uint2*)(p + 8 * PXB);
                }
#pragma unroll
                for (int nt = 0; nt < NTL; nt++) {
                    uint2 B = *(const uint2*)(wsb + ((c * OC) + nt * 8 + g) * 32 + 8 * t);
#pragma unroll
                    for (int m = 0; m < 2; m++)
                        mma_k32(acc[m][nt], A[m][0].x, A[m][1].x, A[m][0].y, A[m][1].y,
                                B.x, B.y);
                }
            }
#pragma unroll
            for (int m = 0; m < 2; m++)
#pragma unroll
                for (int r = 0; r < 2; r++) {
                    const int pxl = m * 16 + r * 8 + g;
#pragma unroll
                    for (int nt = 0; nt < NTL; nt++) {
                        int c0 = __float2int_rn(fmaf((float)acc[m][nt][2 * r + 0], csa, bva[nt][0]));
                        int c1 = __float2int_rn(fmaf((float)acc[m][nt][2 * r + 1], csa, bva[nt][1]));
                        c0 = max(min(c0, 127), 0);
                        c1 = max(min(c1, 127), 0);
                        unsigned short pk = (unsigned short)((unsigned char)lut[c0] |
                                            ((unsigned)(unsigned char)lut[c1] << 8));
                        *(unsigned short*)(stg[w] + pxl * OC + nt * 8 + 2 * t) = pk;
                    }
                }
            __syncwarp();
#pragma unroll
            for (int i = lane; i < 2 * OC; i += 32) {
                const int pxl = (16 * i) / OC;
                const int x = xw + pxl;
                if (x < Wout)
                    *(uint4*)(out + ((long)b * BSo + (long)y * RSo + x) * OC + (16 * i) % OC) =
                        ((const uint4*)stg[w])[i];
            }
            __syncwarp();
        }
    } else {
        // ========== dp4a path: thread = pixel, prefetched coalesced LDG.128 ==========
        const int xd = bx * 128 + tid;
#pragma unroll 1
        for (int yi = 0; yi < YB; yi++) {
            const int y = by * YB + yi;
            if (y >= Hout) break;
            int acc[OC];
#pragma unroll
            for (int j = 0; j < OC; j++) acc[j] = 0;

            const signed char* base =
                in + ((long)b * BSi + (long)(y - PAD) * RSi + (xd - PAD)) * PXB;
            uint4 va = *(const uint4*)(base + s_off[0]);
            uint4 vb = *(const uint4*)(base + s_off[1]);
#pragma unroll 1
            for (int c = 0; c < NCH; c++) {
                uint4 na, nb;  // prefetch next chunk before consuming current
                if (c + 1 < NCH) {
                    na = *(const uint4*)(base + s_off[2 * c + 2]);
                    nb = *(const uint4*)(base + s_off[2 * c + 3]);
                }
                int v[8] = {(int)va.x, (int)va.y, (int)va.z, (int)va.w,
                            (int)vb.x, (int)vb.y, (int)vb.z, (int)vb.w};
                const int* wrow = (const int*)wsb + c * OC * 8;
#pragma unroll
                for (int j = 0; j < OC; j++) {
                    int4 w0 = ((const int4*)(wrow + j * 8))[0];
                    int4 w1 = ((const int4*)(wrow + j * 8))[1];
                    int a = acc[j];
                    a = __dp4a(v[0], w0.x, a);
                    a = __dp4a(v[1], w0.y, a);
                    a = __dp4a(v[2], w0.z, a);
                    a = __dp4a(v[3], w0.w, a);
                    a = __dp4a(v[4], w1.x, a);
                    a = __dp4a(v[5], w1.y, a);
                    a = __dp4a(v[6], w1.z, a);
                    a = __dp4a(v[7], w1.w, a);
                    acc[j] = a;
                }
                va = na;
                vb = nb;
            }
            if (xd < Wout) {
                unsigned bytes[OC / 4];
#pragma unroll
                for (int q = 0; q < OC / 4; q++) {
                    unsigned r = 0;
#pragma unroll
                    for (int k = 0; k < 4; k++) {
                        int j = q * 4 + k;
                        int cc = __float2int_rn(fmaf((float)acc[j], csa, s_bva[j]));
                        r |= ((unsigned)(unsigned char)lut[max(min(cc, 127), 0)]) << (8 * k);
                    }
                    bytes[q] = r;
                }
                signed char* dst = out + ((long)b * BSo + (long)y * RSo + xd) * OC;
#pragma unroll
                for (int q = 0; q < OC / 16; q++)
                    ((uint4*)dst)[q] = ((const uint4*)bytes)[q];
            }
        }
    }
}

// ---------------- maxpool ----------------
__global__ void pool_kernel(const float* __restrict__ sc) {
    __shared__ signed char lut[128];
    const int tid = threadIdx.x;
    if (tid < 128) lut[tid] = (signed char)(int)fq_q((float)tid * sc[6], sc[7]);
    __syncthreads();
    int idx = blockIdx.x * 256 + tid;
    if (idx >= 32 * 127 * 127 * 2) return;
    int half = idx & 1, p = idx >> 1;
    int x = p % 127, y = (p / 127) % 127, b = p / (127 * 127);
    const signed char* src = g_c3 + (((size_t)(b * 254 + 2 * y)) * 254 + 2 * x) * 32 + half * 16;
    int4 v00 = *(const int4*)src;
    int4 v01 = *(const int4*)(src + 32);
    int4 v10 = *(const int4*)(src + 254 * 32);
    int4 v11 = *(const int4*)(src + 254 * 32 + 32);
    int mw[4];
    mw[0] = __vmaxs4(__vmaxs4(v00.x, v01.x), __vmaxs4(v10.x, v11.x));
    mw[1] = __vmaxs4(__vmaxs4(v00.y, v01.y), __vmaxs4(v10.y, v11.y));
    mw[2] = __vmaxs4(__vmaxs4(v00.z, v01.z), __vmaxs4(v10.z, v11.z));
    mw[3] = __vmaxs4(__vmaxs4(v00.w, v01.w), __vmaxs4(v10.w, v11.w));
    unsigned rw[4];
#pragma unroll
    for (int ww = 0; ww < 4; ww++) {
        unsigned r = 0;
#pragma unroll
        for (int k = 0; k < 4; k++)
            r |= ((unsigned)(unsigned char)lut[sbyte(mw[ww], k)]) << (8 * k);
        rw[ww] = r;
    }
    *(uint4*)(g_pool + (((size_t)(b * 127 + y)) * 132 + x) * 32 + half * 16) =
        make_uint4(rw[0], rw[1], rw[2], rw[3]);
}

// ---------------- gap + fc ----------------
__global__ void gap_kernel(const float* __restrict__ sc) {
    __shared__ int red[256][16];
    const int b = blockIdx.x, tid = threadIdx.x;
    int acc[16];
#pragma unroll
    for (int k = 0; k < 16; k++) acc[k] = 0;
    const signed char* p = g_c4 + (size_t)b * 125 * 125 * 16;
    for (int i = tid; i < 125 * 125; i += 256) {
        int4 v = *(const int4*)(p + (size_t)i * 16);
        int wv[4] = {v.x, v.y, v.z, v.w};
#pragma unroll
        for (int j = 0; j < 4; j++)
#pragma unroll
            for (int k = 0; k < 4; k++) acc[j * 4 + k] += sbyte(wv[j], k);
    }
#pragma unroll
    for (int k = 0; k < 16; k++) red[tid][k] = acc[k];
    __syncthreads();
    for (int s = 128; s > 0; s >>= 1) {
        if (tid < s)
#pragma unroll
            for (int k = 0; k < 16; k++) red[tid][k] += red[tid + s][k];
        __syncthreads();
    }
    if (tid < 16)
        g_feat[b * 16 + tid] = fq(__fdiv_rn((float)red[0][tid] * sc[9], 15625.0f), sc[10]);
}

__global__ void fc_kernel(const float* __restrict__ bias, float* __restrict__ out) {
    int t = threadIdx.x;
    if (t >= 320) return;
    int b = t / 10, j = t % 10;
    float s = bias[j];
#pragma unroll
    for (int k = 0; k < 16; k++) s += g_feat[b * 16 + k] * g_qwc[k * 10 + j];
    out[b * 10 + j] = s;
}

// ---------------- launcher ----------------
extern "C" void kernel_launch(void* const* d_in, const int* in_sizes, int n_in,
                              void* d_out, int out_size) {
    const float* x  = (const float*)d_in[0];
    const float* w1 = (const float*)d_in[1];
    const float* b1 = (const float*)d_in[2];
    const float* w2 = (const float*)d_in[3];
    const float* b2 = (const float*)d_in[4];
    const float* w3 = (const float*)d_in[5];
    const float* b3 = (const float*)d_in[6];
    const float* w4 = (const float*)d_in[7];
    const float* b4 = (const float*)d_in[8];
    const float* wc = (const float*)d_in[9];
    const float* bc = (const float*)d_in[10];
    const float* sc = (const float*)d_in[11];
    float* out = (float*)d_out;

    signed char *pad16, *pad32, *poolb, *qw2, *qw3, *qw4, *c3, *c4;
    float* wsc;
    cudaGetSymbolAddress((void**)&pad16, g_pad16);
    cudaGetSymbolAddress((void**)&pad32, g_pad32);
    cudaGetSymbolAddress((void**)&poolb, g_pool);
    cudaGetSymbolAddress((void**)&qw2, g_qw2);
    cudaGetSymbolAddress((void**)&qw3, g_qw3);
    cudaGetSymbolAddress((void**)&qw4, g_qw4);
    cudaGetSymbolAddress((void**)&wsc, g_wscale);
    cudaGetSymbolAddress((void**)&c3, g_c3);
    cudaGetSymbolAddress((void**)&c4, g_c4);

    // 1. prep
    prep_kernel<<<2053 + 1031, 256>>>(x, w1, w2, w3, w4, wc, sc);

    // 2. conv1
    conv1_kernel<<<(32 * 254 * 254 + 255) / 256, 256>>>(b1, sc);

    // 3. conv2: 16->32 3x3 same, hybrid split 22 IMMA / 10 dp4a
    conv_hyb_kernel<16, 32, 3, 5, 8><<<dim3(2, 32, 32), 128>>>(
        pad16 + (size_t)ORG * 16, (long)HSP * WSP, WSP, 1, qw2, b2,
        pad32 + (size_t)ORG * 32, (long)HSP * WSP, WSP, 254, 254, sc, wsc + 1, 2, 3, 4, 22);

    // 4. conv3: 32->32 5x5 same, hybrid split 22/10   [profiled launch]
    conv_hyb_kernel<32, 32, 5, 25, 8><<<dim3(2, 32, 32), 128>>>(
        pad32 + (size_t)ORG * 32, (long)HSP * WSP, WSP, 2, qw3, b3,
        c3, (long)254 * 254, 254, 254, 254, sc, wsc + 2, 4, 5, 6, 22);

    // 5. maxpool
    pool_kernel<<<(32 * 127 * 127 * 2 + 255) / 256, 256>>>(sc);

    // 6. conv4: 32->16 3x3 valid, hybrid split 11/5
    conv_hyb_kernel<32, 16, 3, 9, 8><<<dim3(1, 16, 32), 128>>>(
        poolb, (long)127 * 132, 132, 0, qw4, b4,
        c4, (long)125 * 125, 125, 125, 125, sc, wsc + 3, 7, 8, 9, 11);

    // 7-8. gap + fc
    gap_kernel<<<32, 256>>>(sc);
    fc_kernel<<<1, 512>>>(bc, out);
}

// round 13
// speedup vs baseline: 4.4695x; 1.0747x over previous
#include <cuda_runtime.h>
#include <cstdint>

#define DI __device__ __forceinline__

DI float fq_q(float x, float s) {
    float q = rintf(__fdiv_rn(x, s));
    return fminf(fmaxf(q, -128.0f), 127.0f);
}
DI float fq(float x, float s) { return fq_q(x, s) * s; }
DI int sbyte(int w, int k) { return (int)((signed char)(w >> (8 * k))); }

#define WSP 264
#define HSP 260
#define ORG (3 * 264 + 3)

// ---------------- scratch ----------------
__device__ __align__(16) signed char g_pad16[(size_t)32 * HSP * WSP * 16];
__device__ __align__(16) signed char g_pad32[(size_t)32 * HSP * WSP * 32];
__device__ __align__(16) signed char g_c3[(size_t)32 * 254 * 254 * 32];
__device__ __align__(16) signed char g_pool[(size_t)32 * 127 * 132 * 32];
__device__ __align__(16) signed char g_c4[(size_t)32 * 125 * 125 * 16];
__device__ __align__(16) signed char g_in0[(size_t)32 * 256 * 256];
__device__ __align__(16) int g_qw1[9 * 16];
__device__ __align__(16) signed char g_qw2[5 * 32 * 32];    // [chunk][oc][32B] paired taps
__device__ __align__(16) signed char g_qw3[25 * 32 * 32];   // [tap][oc][ic]
__device__ __align__(16) signed char g_qw4[9 * 16 * 32];    // [tap][oc][ic]
__device__ float g_qwc[160], g_wscale[8], g_feat[512];

DI void mma_k32(int d[4], unsigned a0, unsigned a1, unsigned a2, unsigned a3,
                unsigned b0, unsigned b1) {
    asm volatile(
        "mma.sync.aligned.m16n8k32.row.col.s32.s8.s8.s32 "
        "{%0,%1,%2,%3}, {%4,%5,%6,%7}, {%8,%9}, {%0,%1,%2,%3};\n"
        : "+r"(d[0]), "+r"(d[1]), "+r"(d[2]), "+r"(d[3])
        : "r"(a0), "r"(a1), "r"(a2), "r"(a3), "r"(b0), "r"(b1));
}

// ---------------- prep ----------------
DI float bmax(const float* w, int n, float* red) {
    float m = 0.0f;
    for (int i = threadIdx.x; i < n; i += 256) m = fmaxf(m, fabsf(w[i]));
    red[threadIdx.x] = m;
    __syncthreads();
    for (int s = 128; s > 0; s >>= 1) {
        if (threadIdx.x < s) red[threadIdx.x] = fmaxf(red[threadIdx.x], red[threadIdx.x + s]);
        __syncthreads();
    }
    return red[0];
}

__global__ void prep_kernel(const float* __restrict__ x, const float* __restrict__ w1,
                            const float* __restrict__ w2, const float* __restrict__ w3,
                            const float* __restrict__ w4, const float* __restrict__ wc,
                            const float* __restrict__ sc) {
    __shared__ float red[256];
    const int blk = blockIdx.x, tid = threadIdx.x;
    if (blk < 2048) {
        int i = blk * 256 + tid;
        float4 v = ((const float4*)x)[i];
        float inv = __frcp_rn(sc[0]);
        int c0 = max(min(__float2int_rn(v.x * inv), 127), -128);
        int c1 = max(min(__float2int_rn(v.y * inv), 127), -128);
        int c2 = max(min(__float2int_rn(v.z * inv), 127), -128);
        int c3 = max(min(__float2int_rn(v.w * inv), 127), -128);
        ((int*)g_in0)[i] = (c0 & 0xFF) | ((c1 & 0xFF) << 8) | ((c2 & 0xFF) << 16) |
                           ((c3 & 0xFF) << 24);
    } else if (blk == 2048) {
        float s = __fdiv_rn(bmax(w1, 144, red), 127.0f);
        if (tid == 0) g_wscale[0] = s;
        for (int i = tid; i < 144; i += 256) g_qw1[(i % 9) * 16 + i / 9] = (int)fq_q(w1[i], s);
    } else if (blk == 2049) {  // conv2: 5 paired chunks [c][oc][32B]
        float s = __fdiv_rn(bmax(w2, 4608, red), 127.0f);
        if (tid == 0) g_wscale[1] = s;
        for (int i = tid; i < 5120; i += 256) {
            int j = i & 31, oc = (i >> 5) & 31, c = i >> 10;
            int tap = 2 * c + (j >= 16), ic = j & 15;
            signed char v = 0;
            if (tap < 9)
                v = (signed char)(int)fq_q(w2[((oc * 16 + ic) * 3 + tap / 3) * 3 + tap % 3], s);
            g_qw2[i] = v;
        }
    } else if (blk == 2050) {
        float s = __fdiv_rn(bmax(w3, 25600, red), 127.0f);
        if (tid == 0) g_wscale[2] = s;
        for (int i = tid; i < 25600; i += 256) {
            int ic = i & 31, oc = (i >> 5) & 31, tap = i >> 10;
            g_qw3[i] = (signed char)(int)fq_q(w3[((oc * 32 + ic) * 5 + tap / 5) * 5 + tap % 5], s);
        }
    } else if (blk == 2051) {
        float s = __fdiv_rn(bmax(w4, 4608, red), 127.0f);
        if (tid == 0) g_wscale[3] = s;
        for (int i = tid; i < 4608; i += 256) {
            int ic = i & 31, oc = (i >> 5) & 15, tap = i >> 9;
            g_qw4[i] = (signed char)(int)fq_q(w4[((oc * 32 + ic) * 3 + tap / 3) * 3 + tap % 3], s);
        }
    } else if (blk == 2052) {
        float s = __fdiv_rn(bmax(wc, 160, red), 127.0f);
        for (int i = tid; i < 160; i += 256) g_qwc[(i % 16) * 10 + i / 16] = fq_q(wc[i], s) * s;
    } else {
        int idx = (blk - 2053) * 256 + tid;
        const int ITEMS = 32 * 4124;
        int which = idx >= ITEMS;
        if (which) idx -= ITEMS;
        int b = idx / 4124, i = idx % 4124, pr, pc;
        if (i < 1584) { pc = i % 264; int r = i / 264; pr = (r < 3) ? r : 254 + r; }
        else { int j = i - 1584; pr = 3 + j / 10; int c = j % 10; pc = (c < 3) ? c : 254 + c; }
        size_t px = ((size_t)b * HSP + pr) * WSP + pc;
        uint4 z = make_uint4(0, 0, 0, 0);
        if (!which) {
            *(uint4*)(g_pad16 + px * 16) = z;
        } else {
            uint4* d = (uint4*)(g_pad32 + px * 32);
            d[0] = z; d[1] = z;
        }
    }
}

// ---------------- conv1 ----------------
__global__ void __launch_bounds__(256) conv1_kernel(const float* __restrict__ bias,
                                                    const float* __restrict__ sc) {
    __shared__ int wsm[144];
    __shared__ signed char lut[128];
    __shared__ float bsm[16];
    const int tid = threadIdx.x;
    const float sa = sc[1], sb = sc[2];
    if (tid < 128) lut[tid] = (signed char)(int)fq_q((float)tid * sa, sb);
    if (tid < 144) wsm[tid] = g_qw1[tid];
    if (tid >= 144 && tid < 160) bsm[tid - 144] = bias[tid - 144];
    __syncthreads();
    int idx = blockIdx.x * 256 + tid;
    if (idx >= 32 * 254 * 254) return;
    int x = idx % 254, y = (idx / 254) % 254, b = idx / (254 * 254);
    const signed char* base = g_in0 + (size_t)b * 65536;
    int v[9];
#pragma unroll
    for (int ky = 0; ky < 3; ky++)
#pragma unroll
        for (int kx = 0; kx < 3; kx++)
            v[ky * 3 + kx] = (int)base[(size_t)(y + ky) * 256 + x + kx];
    int acc[16];
#pragma unroll
    for (int j = 0; j < 16; j++) acc[j] = 0;
#pragma unroll
    for (int t = 0; t < 9; t++)
#pragma unroll
        for (int j = 0; j < 16; j++) acc[j] += v[t] * wsm[t * 16 + j];
    const float csa = __fdiv_rn(sc[0] * g_wscale[0], sa);
    unsigned wds[4];
#pragma unroll
    for (int g = 0; g < 4; g++) {
        unsigned wd = 0;
#pragma unroll
        for (int k = 0; k < 4; k++) {
            int j = g * 4 + k;
            int c = __float2int_rn(fmaf((float)acc[j], csa, __fdiv_rn(bsm[j], sa)));
            wd |= ((unsigned)(unsigned char)lut[max(min(c, 127), 0)]) << (8 * k);
        }
        wds[g] = wd;
    }
    *(uint4*)(g_pad16 + (((size_t)b * HSP + y + 3) * WSP + x + 3) * 16) =
        make_uint4(wds[0], wds[1], wds[2], wds[3]);
}

// ---------------- intra-CTA hybrid conv ----------------
// 256 threads: warps 0-3 = IMMA on rows [0,YBI); warps 4-7 = dp4a on rows [YBI,YBI+YBD)
template <int PXB, int OC, int K, int NCH, int YBI, int YBD>
__global__ void __launch_bounds__(256) conv_mix_kernel(
    const signed char* __restrict__ in, long BSi, int RSi, int PAD,
    const signed char* __restrict__ wq, const float* __restrict__ bias,
    signed char* __restrict__ out, long BSo, int RSo, int Wout, int Hout,
    const float* __restrict__ sc, const float* __restrict__ wsc,
    int s_in, int s_a, int s_b) {
    constexpr int NTL = OC / 8;
    constexpr int KK = K * K;
    constexpr int NWB = NCH * OC * 32;
    constexpr int YBT = YBI + YBD;

    __shared__ int wsm[NWB / 4];
    __shared__ signed char lut[128];
    __shared__ float s_bva[OC];
    __shared__ int s_off[NCH * 2];
    __shared__ __align__(16) signed char stg[4][32 * OC];

    const int tid = threadIdx.x;
    const float sa = sc[s_a];
    if (tid < 128) lut[tid] = (signed char)(int)fq_q((float)tid * sa, sc[s_b]);
    if (tid < OC) s_bva[tid] = __fdiv_rn(bias[tid], sa);
    if (tid < NCH) {
        int o0, o1;
        if (PXB == 16) {
            int t0 = 2 * tid;
            int t1 = (2 * tid + 1 < KK) ? 2 * tid + 1 : 2 * tid;
            o0 = ((t0 / K) * RSi + t0 % K) * 16;
            o1 = ((t1 / K) * RSi + t1 % K) * 16;
        } else {
            o0 = ((tid / K) * RSi + tid % K) * 32;
            o1 = o0 + 16;
        }
        s_off[2 * tid] = o0;
        s_off[2 * tid + 1] = o1;
    }
    for (int i = tid; i < NWB / 4; i += 256) wsm[i] = ((const int*)wq)[i];
    __syncthreads();

    const int bx = blockIdx.x, by = blockIdx.y, b = blockIdx.z;
    const signed char* wsb = (const signed char*)wsm;
    const float csa = __fdiv_rn(sc[s_in] * wsc[0], sa);
    const int ybase = by * YBT;

    if (tid < 128) {
        // ===================== IMMA half (warps 0-3) =====================
        const int w = tid >> 5, lane = tid & 31;
        const int g = lane >> 2, t = lane & 3;
        const int xw = bx * 128 + w * 32;
        float bva[NTL][2];
#pragma unroll
        for (int nt = 0; nt < NTL; nt++) {
            bva[nt][0] = __fdiv_rn(bias[nt * 8 + 2 * t], sa);
            bva[nt][1] = __fdiv_rn(bias[nt * 8 + 2 * t + 1], sa);
        }
#pragma unroll 1
        for (int yi = 0; yi < YBI; yi++) {
            const int y = ybase + yi;
            if (y >= Hout) break;
            int acc[2][NTL][4];
#pragma unroll
            for (int m = 0; m < 2; m++)
#pragma unroll
                for (int nt = 0; nt < NTL; nt++)
#pragma unroll
                    for (int k = 0; k < 4; k++) acc[m][nt][k] = 0;

            const signed char* base =
                in + ((long)b * BSi + (long)(y - PAD) * RSi + (xw - PAD)) * PXB;
#pragma unroll
            for (int c = 0; c < NCH; c++) {
                int t0, t1;
                long o0, o1;
                if (PXB == 16) {
                    t0 = 2 * c;
                    t1 = (2 * c + 1 < KK) ? 2 * c + 1 : 2 * c;
                    o0 = ((long)(t0 / K) * RSi + t0 % K) * 16;
                    o1 = ((long)(t1 / K) * RSi + t1 % K) * 16;
                } else {
                    o0 = ((long)(c / K) * RSi + c % K) * 32;
                    o1 = o0 + 16;
                }
                const long osel = (t < 2) ? o0 : o1;
                const long boff = osel + 8 * (t & 1);
                uint2 A[2][2];
#pragma unroll
                for (int m = 0; m < 2; m++) {
                    const signed char* p = base + (m * 16 + g) * PXB + boff;
                    A[m][0] = *(const uint2*)p;
                    A[m][1] = *(const uint2*)(p + 8 * PXB);
                }
#pragma unroll
                for (int nt = 0; nt < NTL; nt++) {
                    uint2 B = *(const uint2*)(wsb + ((c * OC) + nt * 8 + g) * 32 + 8 * t);
#pragma unroll
                    for (int m = 0; m < 2; m++)
                        mma_k32(acc[m][nt], A[m][0].x, A[m][1].x, A[m][0].y, A[m][1].y,
                                B.x, B.y);
                }
            }
#pragma unroll
            for (int m = 0; m < 2; m++)
#pragma unroll
                for (int r = 0; r < 2; r++) {
                    const int pxl = m * 16 + r * 8 + g;
#pragma unroll
                    for (int nt = 0; nt < NTL; nt++) {
                        int c0 = __float2int_rn(fmaf((float)acc[m][nt][2 * r + 0], csa, bva[nt][0]));
                        int c1 = __float2int_rn(fmaf((float)acc[m][nt][2 * r + 1], csa, bva[nt][1]));
                        c0 = max(min(c0, 127), 0);
                        c1 = max(min(c1, 127), 0);
                        unsigned short pk = (unsigned short)((unsigned char)lut[c0] |
                                            ((unsigned)(unsigned char)lut[c1] << 8));
                        *(unsigned short*)(stg[w] + pxl * OC + nt * 8 + 2 * t) = pk;
                    }
                }
            __syncwarp();
#pragma unroll
            for (int i = lane; i < 2 * OC; i += 32) {
                const int pxl = (16 * i) / OC;
                const int x = xw + pxl;
                if (x < Wout)
                    *(uint4*)(out + ((long)b * BSo + (long)y * RSo + x) * OC + (16 * i) % OC) =
                        ((const uint4*)stg[w])[i];
            }
            __syncwarp();
        }
    } else {
        // ===================== dp4a half (warps 4-7) =====================
        const int t2 = tid - 128;
        const int xd = bx * 128 + t2;
#pragma unroll 1
        for (int yi = 0; yi < YBD; yi++) {
            const int y = ybase + YBI + yi;
            if (y >= Hout) break;
            int acc[OC];
#pragma unroll
            for (int j = 0; j < OC; j++) acc[j] = 0;

            const signed char* base =
                in + ((long)b * BSi + (long)(y - PAD) * RSi + (xd - PAD)) * PXB;
            uint4 va = *(const uint4*)(base + s_off[0]);
            uint4 vb = *(const uint4*)(base + s_off[1]);
#pragma unroll 1
            for (int c = 0; c < NCH; c++) {
                uint4 na, nb;  // prefetch next chunk
                if (c + 1 < NCH) {
                    na = *(const uint4*)(base + s_off[2 * c + 2]);
                    nb = *(const uint4*)(base + s_off[2 * c + 3]);
                }
                int v[8] = {(int)va.x, (int)va.y, (int)va.z, (int)va.w,
                            (int)vb.x, (int)vb.y, (int)vb.z, (int)vb.w};
                const int* wrow = (const int*)wsb + c * OC * 8;
#pragma unroll
                for (int j = 0; j < OC; j++) {
                    int4 w0 = ((const int4*)(wrow + j * 8))[0];
                    int4 w1 = ((const int4*)(wrow + j * 8))[1];
                    int a = acc[j];
                    a = __dp4a(v[0], w0.x, a);
                    a = __dp4a(v[1], w0.y, a);
                    a = __dp4a(v[2], w0.z, a);
                    a = __dp4a(v[3], w0.w, a);
                    a = __dp4a(v[4], w1.x, a);
                    a = __dp4a(v[5], w1.y, a);
                    a = __dp4a(v[6], w1.z, a);
                    a = __dp4a(v[7], w1.w, a);
                    acc[j] = a;
                }
                va = na;
                vb = nb;
            }
            if (xd < Wout) {
                unsigned bytes[OC / 4];
#pragma unroll
                for (int q = 0; q < OC / 4; q++) {
                    unsigned r = 0;
#pragma unroll
                    for (int k = 0; k < 4; k++) {
                        int j = q * 4 + k;
                        int cc = __float2int_rn(fmaf((float)acc[j], csa, s_bva[j]));
                        r |= ((unsigned)(unsigned char)lut[max(min(cc, 127), 0)]) << (8 * k);
                    }
                    bytes[q] = r;
                }
                signed char* dst = out + ((long)b * BSo + (long)y * RSo + xd) * OC;
#pragma unroll
                for (int q = 0; q < OC / 16; q++)
                    ((uint4*)dst)[q] = ((const uint4*)bytes)[q];
            }
        }
    }
}

// ---------------- maxpool ----------------
__global__ void pool_kernel(const float* __restrict__ sc) {
    __shared__ signed char lut[128];
    const int tid = threadIdx.x;
    if (tid < 128) lut[tid] = (signed char)(int)fq_q((float)tid * sc[6], sc[7]);
    __syncthreads();
    int idx = blockIdx.x * 256 + tid;
    if (idx >= 32 * 127 * 127 * 2) return;
    int half = idx & 1, p = idx >> 1;
    int x = p % 127, y = (p / 127) % 127, b = p / (127 * 127);
    const signed char* src = g_c3 + (((size_t)(b * 254 + 2 * y)) * 254 + 2 * x) * 32 + half * 16;
    int4 v00 = *(const int4*)src;
    int4 v01 = *(const int4*)(src + 32);
    int4 v10 = *(const int4*)(src + 254 * 32);
    int4 v11 = *(const int4*)(src + 254 * 32 + 32);
    int mw[4];
    mw[0] = __vmaxs4(__vmaxs4(v00.x, v01.x), __vmaxs4(v10.x, v11.x));
    mw[1] = __vmaxs4(__vmaxs4(v00.y, v01.y), __vmaxs4(v10.y, v11.y));
    mw[2] = __vmaxs4(__vmaxs4(v00.z, v01.z), __vmaxs4(v10.z, v11.z));
    mw[3] = __vmaxs4(__vmaxs4(v00.w, v01.w), __vmaxs4(v10.w, v11.w));
    unsigned rw[4];
#pragma unroll
    for (int ww = 0; ww < 4; ww++) {
        unsigned r = 0;
#pragma unroll
        for (int k = 0; k < 4; k++)
            r |= ((unsigned)(unsigned char)lut[sbyte(mw[ww], k)]) << (8 * k);
        rw[ww] = r;
    }
    *(uint4*)(g_pool + (((size_t)(b * 127 + y)) * 132 + x) * 32 + half * 16) =
        make_uint4(rw[0], rw[1], rw[2], rw[3]);
}

// ---------------- gap + fc ----------------
__global__ void gap_kernel(const float* __restrict__ sc) {
    __shared__ int red[256][16];
    const int b = blockIdx.x, tid = threadIdx.x;
    int acc[16];
#pragma unroll
    for (int k = 0; k < 16; k++) acc[k] = 0;
    const signed char* p = g_c4 + (size_t)b * 125 * 125 * 16;
    for (int i = tid; i < 125 * 125; i += 256) {
        int4 v = *(const int4*)(p + (size_t)i * 16);
        int wv[4] = {v.x, v.y, v.z, v.w};
#pragma unroll
        for (int j = 0; j < 4; j++)
#pragma unroll
            for (int k = 0; k < 4; k++) acc[j * 4 + k] += sbyte(wv[j], k);
    }
#pragma unroll
    for (int k = 0; k < 16; k++) red[tid][k] = acc[k];
    __syncthreads();
    for (int s = 128; s > 0; s >>= 1) {
        if (tid < s)
#pragma unroll
            for (int k = 0; k < 16; k++) red[tid][k] += red[tid + s][k];
        __syncthreads();
    }
    if (tid < 16)
        g_feat[b * 16 + tid] = fq(__fdiv_rn((float)red[0][tid] * sc[9], 15625.0f), sc[10]);
}

__global__ void fc_kernel(const float* __restrict__ bias, float* __restrict__ out) {
    int t = threadIdx.x;
    if (t >= 320) return;
    int b = t / 10, j = t % 10;
    float s = bias[j];
#pragma unroll
    for (int k = 0; k < 16; k++) s += g_feat[b * 16 + k] * g_qwc[k * 10 + j];
    out[b * 10 + j] = s;
}

// ---------------- launcher ----------------
extern "C" void kernel_launch(void* const* d_in, const int* in_sizes, int n_in,
                              void* d_out, int out_size) {
    const float* x  = (const float*)d_in[0];
    const float* w1 = (const float*)d_in[1];
    const float* b1 = (const float*)d_in[2];
    const float* w2 = (const float*)d_in[3];
    const float* b2 = (const float*)d_in[4];
    const float* w3 = (const float*)d_in[5];
    const float* b3 = (const float*)d_in[6];
    const float* w4 = (const float*)d_in[7];
    const float* b4 = (const float*)d_in[8];
    const float* wc = (const float*)d_in[9];
    const float* bc = (const float*)d_in[10];
    const float* sc = (const float*)d_in[11];
    float* out = (float*)d_out;

    signed char *pad16, *pad32, *poolb, *qw2, *qw3, *qw4, *c3, *c4;
    float* wsc;
    cudaGetSymbolAddress((void**)&pad16, g_pad16);
    cudaGetSymbolAddress((void**)&pad32, g_pad32);
    cudaGetSymbolAddress((void**)&poolb, g_pool);
    cudaGetSymbolAddress((void**)&qw2, g_qw2);
    cudaGetSymbolAddress((void**)&qw3, g_qw3);
    cudaGetSymbolAddress((void**)&qw4, g_qw4);
    cudaGetSymbolAddress((void**)&wsc, g_wscale);
    cudaGetSymbolAddress((void**)&c3, g_c3);
    cudaGetSymbolAddress((void**)&c4, g_c4);

    // 1. prep
    prep_kernel<<<2053 + 1031, 256>>>(x, w1, w2, w3, w4, wc, sc);

    // 2. conv1
    conv1_kernel<<<(32 * 254 * 254 + 255) / 256, 256>>>(b1, sc);

    // 3. conv2: 16->32 3x3 same, intra-CTA hybrid 8 IMMA rows + 4 dp4a rows
    conv_mix_kernel<16, 32, 3, 5, 8, 4><<<dim3(2, 22, 32), 256>>>(
        pad16 + (size_t)ORG * 16, (long)HSP * WSP, WSP, 1, qw2, b2,
        pad32 + (size_t)ORG * 32, (long)HSP * WSP, WSP, 254, 254, sc, wsc + 1, 2, 3, 4);

    // 4. conv3: 32->32 5x5 same, intra-CTA hybrid 8+4   [profiled launch]
    conv_mix_kernel<32, 32, 5, 25, 8, 4><<<dim3(2, 22, 32), 256>>>(
        pad32 + (size_t)ORG * 32, (long)HSP * WSP, WSP, 2, qw3, b3,
        c3, (long)254 * 254, 254, 254, 254, sc, wsc + 2, 4, 5, 6);

    // 5. maxpool
    pool_kernel<<<(32 * 127 * 127 * 2 + 255) / 256, 256>>>(sc);

    // 6. conv4: 32->16 3x3 valid, intra-CTA hybrid 8+4
    conv_mix_kernel<32, 16, 3, 9, 8, 4><<<dim3(1, 11, 32), 256>>>(
        poolb, (long)127 * 132, 132, 0, qw4, b4,
        c4, (long)125 * 125, 125, 125, 125, sc, wsc + 3, 7, 8, 9);

    // 7-8. gap + fc
    gap_kernel<<<32, 256>>>(sc);
    fc_kernel<<<1, 512>>>(bc, out);
}